// round 17
// baseline (speedup 1.0000x reference)
#include <cuda_runtime.h>
#include <cuda_fp16.h>
#include <math.h>
#include <stdint.h>

#define B_    8
#define C_    96
#define C2_   192
#define NPIX  16384
#define HEADS_ 6

__device__ __forceinline__ void mma16(float* c, const uint32_t* a, uint32_t b0, uint32_t b1) {
    asm volatile("mma.sync.aligned.m16n8k16.row.col.f32.f16.f16.f32 "
                 "{%0,%1,%2,%3}, {%4,%5,%6,%7}, {%8,%9}, {%0,%1,%2,%3};"
                 : "+f"(c[0]), "+f"(c[1]), "+f"(c[2]), "+f"(c[3])
                 : "r"(a[0]), "r"(a[1]), "r"(a[2]), "r"(a[3]), "r"(b0), "r"(b1));
}
__device__ __forceinline__ uint32_t sm2u(const void* p) {
    return (uint32_t)__cvta_generic_to_shared(p);
}
__device__ __forceinline__ void ldsm4(uint32_t& a, uint32_t& b, uint32_t& c, uint32_t& d,
                                      uint32_t addr) {
    asm volatile("ldmatrix.sync.aligned.m8n8.x4.shared.b16 {%0,%1,%2,%3}, [%4];"
                 : "=r"(a), "=r"(b), "=r"(c), "=r"(d) : "r"(addr));
}
__device__ __forceinline__ void ldsm4t(uint32_t& a, uint32_t& b, uint32_t& c, uint32_t& d,
                                       uint32_t addr) {
    asm volatile("ldmatrix.sync.aligned.m8n8.x4.trans.shared.b16 {%0,%1,%2,%3}, [%4];"
                 : "=r"(a), "=r"(b), "=r"(c), "=r"(d) : "r"(addr));
}

// ---- device-global scratch ----
__device__ __half g_xh [B_ * C_  * NPIX];
__device__ __half g_yh [B_ * C_  * NPIX];
__device__ __half g_t  [B_ * C2_ * NPIX];
__device__ __half g_t2 [B_ * C2_ * NPIX];
__device__ __half g_qv [B_ * C2_ * NPIX];
__device__ __half g_kv [B_ * C2_ * NPIX];
__device__ __half g_v  [B_ * C_  * NPIX];
__device__ float g_attn[B_ * HEADS_ * 16 * 16];
__device__ float g_gram[B_ * HEADS_ * 16 * 16];
__device__ float g_nrm [B_ * HEADS_ * 32];
__device__ __half g_wq  [3 * 192 * 40];
__device__ __half g_wk  [3 * 192 * 40];
__device__ __half g_wft [12 * 9 * 96 * 16];
__device__ __half g_wfin[B_ * 9 * 192 * 40];

__device__ __host__ __forceinline__ int pos16(int k) {
    return 4 * ((k >> 1) & 3) + 2 * ((k >> 3) & 1) + (k & 1);
}

#define APITCH 40
#define BPITCH 136
#define GABUF  (192 * APITCH)
#define GBBUF  (32 * BPITCH)
#define GBUFSZ (GABUF + GBBUF)
#define SMEM_G (2 * GBUFSZ * 2)          // 48128 bytes

// ============== merged q/k 1x1 GEMM: fp32 in, fp16 out + write-through ==============
__global__ __launch_bounds__(768, 1)
void mma_gemm_qk(const float* __restrict__ x, const float* __restrict__ y,
                 const __half* __restrict__ Wq, const __half* __restrict__ Wk)
{
    extern __shared__ __half smh[];
    const int tid = threadIdx.x;
    const int wid = tid >> 5, lane = tid & 31;
    const int mw = wid >> 1, nw = wid & 1;
    const int r = lane >> 2, cl = lane & 3;
    const int z = blockIdx.y;
    const int b = z >> 1, br = z & 1;
    const int n0 = blockIdx.x * 128;

    const float* in  = br ? y : x;
    const __half* W  = br ? Wk : Wq;
    __half* outp     = br ? g_t2 : g_t;
    __half* wt       = br ? g_yh : g_xh;

    float acc[8][4];
#pragma unroll
    for (int j = 0; j < 8; j++)
#pragma unroll
        for (int q = 0; q < 4; q++) acc[j][q] = 0.f;

    auto stage = [&](int kc, int buf) {
        __half* sA = smh + buf * GBUFSZ;
        __half* sB = sA + GABUF;
        {
            const uint4* src = (const uint4*)(W + (size_t)kc * GABUF);
            uint4* dst = (uint4*)sA;
            for (int i = tid; i < GABUF / 8; i += 768) dst[i] = src[i];
        }
        int cg0 = kc * 32;
        for (int i = tid; i < 512; i += 768) {
            int c = i >> 4, q = i & 15;
            size_t goff = ((size_t)(b * 96 + cg0 + c)) * NPIX + n0 + q * 8;
            const float4* fp = (const float4*)(in + goff);
            float4 f0 = fp[0], f1 = fp[1];
            union { uint4 u; __half2 h[4]; } pk;
            pk.h[0] = __floats2half2_rn(f0.x, f0.y);
            pk.h[1] = __floats2half2_rn(f0.z, f0.w);
            pk.h[2] = __floats2half2_rn(f1.x, f1.y);
            pk.h[3] = __floats2half2_rn(f1.z, f1.w);
            *(uint4*)(sB + c * BPITCH + q * 8) = pk.u;
            *(uint4*)(wt + goff) = pk.u;          // write-through fp16 copy
        }
    };

    const int a_row = mw * 16 + (lane & 7) + ((lane >> 3) & 1) * 8;
    const int a_ko  = ((lane >> 4) & 1) * 8;
    const int b_krow = (lane & 7) + ((lane >> 3) & 1) * 8;
    const int b_nadd = ((lane >> 4) & 1) * 8;

    stage(0, 0);
    __syncthreads();
    for (int s = 0; s < 3; s++) {
        int buf = s & 1;
        if (s + 1 < 3) stage(s + 1, buf ^ 1);
        const __half* sA = smh + buf * GBUFSZ;
        const __half* sB = sA + GABUF;
#pragma unroll
        for (int ks = 0; ks < 2; ks++) {
            uint32_t af[4];
            ldsm4(af[0], af[1], af[2], af[3],
                  sm2u(sA + a_row * APITCH + ks * 16 + a_ko));
#pragma unroll
            for (int j = 0; j < 4; j++) {
                int px0 = nw * 64 + j * 16 + b_nadd;
                uint32_t b0, b1, b2, b3;
                ldsm4t(b0, b1, b2, b3,
                       sm2u(sB + (ks * 16 + b_krow) * BPITCH + px0));
                mma16(acc[2 * j], af, b0, b1);
                mma16(acc[2 * j + 1], af, b2, b3);
            }
        }
        __syncthreads();
    }

    int oc = mw * 16 + r;
    __half* ob = outp + ((size_t)b * 192 + oc) * NPIX + n0 + nw * 64 + 2 * cl;
#pragma unroll
    for (int nt = 0; nt < 8; nt++) {
        __half* op = ob + nt * 8;
        *(__half2*)op = __floats2half2_rn(acc[nt][0], acc[nt][1]);
        *(__half2*)(op + (size_t)8 * NPIX) = __floats2half2_rn(acc[nt][2], acc[nt][3]);
    }
}

// ============== final GEMM: fp16 in (v | xh | yh), fp32 out ==============
__global__ __launch_bounds__(768, 1)
void mma_gemm(const __half* __restrict__ s0, const __half* __restrict__ s1,
              const __half* __restrict__ s2, const __half* __restrict__ W,
              float* __restrict__ out, int K, int wbstride)
{
    extern __shared__ __half smh[];
    const int tid = threadIdx.x;
    const int wid = tid >> 5, lane = tid & 31;
    const int mw = wid >> 1, nw = wid & 1;
    const int r = lane >> 2, cl = lane & 3;
    const int b = blockIdx.y;
    const int n0 = blockIdx.x * 128;

    float acc[8][4];
#pragma unroll
    for (int j = 0; j < 8; j++)
#pragma unroll
        for (int q = 0; q < 4; q++) acc[j][q] = 0.f;

    const int nsteps = K / 32;
    const __half* Wb = W + (size_t)b * wbstride;

    auto stage = [&](int kc, int buf) {
        __half* sA = smh + buf * GBUFSZ;
        __half* sB = sA + GABUF;
        {
            const uint4* src = (const uint4*)(Wb + (size_t)kc * GABUF);
            uint4* dst = (uint4*)sA;
            for (int i = tid; i < GABUF / 8; i += 768) dst[i] = src[i];
        }
        int cg0 = kc * 32;
        const __half* src = ((cg0 < 96) ? s0 : (cg0 < 192) ? s1 : s2)
                            + ((size_t)b * 96 + (cg0 % 96)) * NPIX + n0;
        for (int i = tid; i < 512; i += 768) {
            int c = i >> 4, q = i & 15;
            *(uint4*)(sB + c * BPITCH + q * 8) =
                *(const uint4*)(src + (size_t)c * NPIX + q * 8);
        }
    };

    const int a_row = mw * 16 + (lane & 7) + ((lane >> 3) & 1) * 8;
    const int a_ko  = ((lane >> 4) & 1) * 8;
    const int b_krow = (lane & 7) + ((lane >> 3) & 1) * 8;
    const int b_nadd = ((lane >> 4) & 1) * 8;

    stage(0, 0);
    __syncthreads();
    for (int s = 0; s < nsteps; s++) {
        int buf = s & 1;
        if (s + 1 < nsteps) stage(s + 1, buf ^ 1);
        const __half* sA = smh + buf * GBUFSZ;
        const __half* sB = sA + GABUF;
#pragma unroll
        for (int ks = 0; ks < 2; ks++) {
            uint32_t af[4];
            ldsm4(af[0], af[1], af[2], af[3],
                  sm2u(sA + a_row * APITCH + ks * 16 + a_ko));
#pragma unroll
            for (int j = 0; j < 4; j++) {
                int px0 = nw * 64 + j * 16 + b_nadd;
                uint32_t b0, b1, b2, b3;
                ldsm4t(b0, b1, b2, b3,
                       sm2u(sB + (ks * 16 + b_krow) * BPITCH + px0));
                mma16(acc[2 * j], af, b0, b1);
                mma16(acc[2 * j + 1], af, b2, b3);
            }
        }
        __syncthreads();
    }

    int oc = mw * 16 + r;
    float* ob = out + ((size_t)b * 192 + oc) * NPIX + n0 + nw * 64 + 2 * cl;
#pragma unroll
    for (int nt = 0; nt < 8; nt++) {
        float* op = ob + nt * 8;
        *(float2*)op = make_float2(acc[nt][0], acc[nt][1]);
        *(float2*)(op + (size_t)8 * NPIX) = make_float2(acc[nt][2], acc[nt][3]);
    }
}

// ============== fuse conv 3x3 (192->96), fp16 k16 MMA ==============
#define FCOLS 132
#define FIN_SZ (4 * FCOLS * 16)
#define SMEM_F (2 * FIN_SZ * 2)           // 33792 bytes

__global__ __launch_bounds__(768, 1)
void fuse_mma(const __half* __restrict__ Wt, const float* __restrict__ bias)
{
    extern __shared__ __half smh[];
    const int tid = threadIdx.x;
    const int wid = tid >> 5, lane = tid & 31;
    const int mw = wid >> 2, nw = wid & 3;
    const int r = lane >> 2, cl = lane & 3;
    const int b = blockIdx.y;
    const int r0 = blockIdx.x * 2;
    const int pr = nw >> 1;
    const int xh = (nw & 1) * 64;

    float acc[8][4];
#pragma unroll
    for (int j = 0; j < 8; j++)
#pragma unroll
        for (int q = 0; q < 4; q++) acc[j][q] = 0.f;

    auto stage_in = [&](int c, int buf) {
        __half* dst = smh + buf * FIN_SZ;
        int icg0 = c * 16;
        const __half* srcbase = (icg0 < 96)
            ? (g_kv + ((size_t)b * C2_ + 96 + icg0) * NPIX)
            : (g_qv + ((size_t)b * C2_ + icg0) * NPIX);
        for (int seg = wid; seg < 64; seg += 24) {
            int ic = seg >> 2, rr = seg & 3;
            int gy = r0 + rr - 1;
            int pp = pos16(ic);
            __half* drow = dst + (rr * FCOLS) * 16 + pp;
            const __half2* s2p = (const __half2*)(srcbase + (size_t)ic * NPIX + gy * 128);
            bool rowok = (unsigned)gy < 128u;
            __half2 zz = __floats2half2_rn(0.f, 0.f);
#pragma unroll
            for (int q = 0; q < 2; q++) {
                int cc = lane + q * 32;
                __half2 v = rowok ? s2p[cc] : zz;
                drow[(1 + 2 * cc) * 16] = __low2half(v);
                drow[(2 + 2 * cc) * 16] = __high2half(v);
            }
            if (lane < 4) {
                int col = (lane == 0) ? 0 : (128 + lane);
                drow[col * 16] = __float2half_rn(0.f);
            }
        }
    };

    stage_in(0, 0);
    __syncthreads();
    for (int c = 0; c < 12; c++) {
        int buf = c & 1;
        if (c + 1 < 12) stage_in(c + 1, buf ^ 1);
        const __half* inb = smh + buf * FIN_SZ;
        const __half* wchunk = Wt + (size_t)c * (9 * 96 * 16);
#pragma unroll
        for (int t = 0; t < 9; t++) {
            int dy = t / 3 - 1, dx = t - (t / 3) * 3 - 1;
            const __half* wp = wchunk + t * (96 * 16);
            uint32_t af[4];
            {
                int row = mw * 16 + r;
                uint2 alo = *(const uint2*)(wp + (size_t)row * 16 + cl * 4);
                uint2 ahi = *(const uint2*)(wp + (size_t)(row + 8) * 16 + cl * 4);
                af[0] = alo.x; af[2] = alo.y;
                af[1] = ahi.x; af[3] = ahi.y;
            }
            const __half* bbase = inb +
                ((size_t)(pr + dy + 1) * FCOLS + (xh + dx + 1 + r)) * 16 + cl * 4;
#pragma unroll
            for (int nt = 0; nt < 8; nt++) {
                uint2 bb = *(const uint2*)(bbase + nt * 8 * 16);
                mma16(acc[nt], af, bb.x, bb.y);
            }
        }
        __syncthreads();
    }

    int oc = mw * 16 + r;
    float bv0 = bias[oc];
    float bv8 = bias[oc + 8];
    __half* ob = g_v + ((size_t)b * C_ + oc) * NPIX + (r0 + pr) * 128 + xh + 2 * cl;
#pragma unroll
    for (int nt = 0; nt < 8; nt++) {
        __half* op = ob + nt * 8;
        *(__half2*)op = __floats2half2_rn(acc[nt][0] + bv0, acc[nt][1] + bv0);
        *(__half2*)(op + (size_t)8 * NPIX) =
            __floats2half2_rn(acc[nt][2] + bv8, acc[nt][3] + bv8);
    }
}

// ======================= packs =======================
__global__ void pack_a(const float* __restrict__ w, __half* __restrict__ dst, int K)
{
    int idx = blockIdx.x * 256 + threadIdx.x;
    if (idx >= 192 * K) return;
    int oc = idx / K, k = idx - oc * K;
    int chunk = k >> 5, kin = k & 31;
    dst[((size_t)chunk * 192 + oc) * APITCH + kin] = __float2half_rn(w[idx]);
}
// pack_fuse also zeroes attention accumulators (merged zero_attn_acc)
__global__ void pack_fuse(const float* __restrict__ wf, __half* __restrict__ dst)
{
    int idx = blockIdx.x * 256 + threadIdx.x;
    if (idx < B_ * HEADS_ * 256) g_gram[idx] = 0.f;
    if (idx < B_ * HEADS_ * 32) g_nrm[idx] = 0.f;
    if (idx >= 12 * 9 * 96 * 16) return;
    int ic16 = idx & 15;
    int rem = idx >> 4;
    int oc = rem % 96; rem /= 96;
    int t = rem % 9;
    int chunk = rem / 9;
    int ic = chunk * 16 + ic16;
    dst[(((size_t)chunk * 9 + t) * 96 + oc) * 16 + pos16(ic16)] =
        __float2half_rn(wf[((size_t)oc * 192 + ic) * 9 + t]);
}
__global__ void pack_wfin(const float* __restrict__ wp, const float* __restrict__ wpos,
                          __half* __restrict__ dst)
{
    int idx = blockIdx.x * 256 + threadIdx.x;
    if (idx >= B_ * C2_ * 288) return;
    int b = idx / (C2_ * 288);
    int rem = idx - b * (C2_ * 288);
    int oc = rem / 288, k = rem - oc * 288;
    float v;
    if (k < 96) {
        int h = k >> 4, d = k & 15;
        float s = 0.f;
#pragma unroll
        for (int i = 0; i < 16; i++)
            s = fmaf(wp[oc * 96 + h * 16 + i],
                     g_attn[(((size_t)b * HEADS_ + h) * 16 + i) * 16 + d], s);
        v = s;
    } else {
        v = wpos[(size_t)oc * 192 + (k - 96)];
    }
    int chunk = k >> 5, kin = k & 31;
    dst[(((size_t)b * 9 + chunk) * 192 + oc) * APITCH + kin] = __float2half_rn(v);
}

// ======= depthwise 3x3, pad 1: 8 px/thread, fp16, both branches =======
__global__ __launch_bounds__(256)
void dw3x3_kernel(const float* __restrict__ wdw0, const float* __restrict__ wdw1)
{
    int z = blockIdx.z;
    int b = z >> 1, br = z & 1;
    int c = blockIdx.y;
    int n8 = (blockIdx.x * 256 + threadIdx.x) * 8;
    int yy = n8 >> 7, x0 = n8 & 127;
    const __half* ip = (br ? g_t2 : g_t) + ((size_t)b * C2_ + c) * NPIX;
    const float* wp = (br ? wdw1 : wdw0) + c * 9;
    __half* op = (br ? g_kv : g_qv) + ((size_t)b * C2_ + c) * NPIX + n8;

    float a[8];
#pragma unroll
    for (int j = 0; j < 8; j++) a[j] = 0.f;
#pragma unroll
    for (int ky = 0; ky < 3; ky++) {
        int gy = yy + ky - 1;
        if ((unsigned)gy >= 128u) continue;
        const __half* row = ip + gy * 128 + x0;
        union { uint4 u; __half2 h[4]; } m;
        m.u = *(const uint4*)row;
        float f[8];
#pragma unroll
        for (int q = 0; q < 4; q++) {
            float2 v = __half22float2(m.h[q]);
            f[2 * q] = v.x; f[2 * q + 1] = v.y;
        }
        float lft = (x0 > 0) ? __half2float(row[-1]) : 0.f;
        float rgt = (x0 < 120) ? __half2float(row[8]) : 0.f;
        float w0 = wp[ky * 3], w1 = wp[ky * 3 + 1], w2 = wp[ky * 3 + 2];
        a[0] = fmaf(w0, lft, fmaf(w1, f[0], fmaf(w2, f[1], a[0])));
#pragma unroll
        for (int j = 1; j < 7; j++)
            a[j] = fmaf(w0, f[j - 1], fmaf(w1, f[j], fmaf(w2, f[j + 1], a[j])));
        a[7] = fmaf(w0, f[6], fmaf(w1, f[7], fmaf(w2, rgt, a[7])));
    }
    union { uint4 u; __half2 h[4]; } o;
#pragma unroll
    for (int q = 0; q < 4; q++) o.h[q] = __floats2half2_rn(a[2 * q], a[2 * q + 1]);
    *(uint4*)op = o.u;
}

// ===== attention part 1: partial gram + partial norms =====
#define GR_NC 256
#define NSPLIT 8
__global__ void attn_part()
{
    __shared__ float sq[16][GR_NC + 2];
    __shared__ float sk[16][GR_NC + 2];
    int h = blockIdx.x, b = blockIdx.y, sp = blockIdx.z;
    int tid = threadIdx.x;
    int i = tid >> 4, j = tid & 15;
    int tgt = tid >> 3;
    int toff = (tid & 7) * 32;
    const __half* qb = g_qv + ((size_t)b * C2_ + h * 16) * NPIX;
    const __half* kb = g_kv + ((size_t)b * C2_ + h * 16) * NPIX;
    float acc = 0.f, np = 0.f;
    int nbeg = sp * (NPIX / NSPLIT), nend = nbeg + NPIX / NSPLIT;
    for (int n0 = nbeg; n0 < nend; n0 += GR_NC) {
        for (int idx = tid; idx < 16 * (GR_NC / 2); idx += 256) {
            int c = idx >> 7, nn2 = idx & 127;
            float2 vq = __half22float2(*(const __half2*)(qb + (size_t)c * NPIX + n0 + 2 * nn2));
            float2 vk = __half22float2(*(const __half2*)(kb + (size_t)c * NPIX + n0 + 2 * nn2));
            sq[c][2 * nn2] = vq.x; sq[c][2 * nn2 + 1] = vq.y;
            sk[c][2 * nn2] = vk.x; sk[c][2 * nn2 + 1] = vk.y;
        }
        __syncthreads();
#pragma unroll 4
        for (int nn = 0; nn < GR_NC; nn++) acc = fmaf(sq[i][nn], sk[j][nn], acc);
        {
            const float* src = (tgt < 16) ? sq[tgt] : sk[tgt - 16];
#pragma unroll 8
            for (int u = 0; u < 32; u++) { float v = src[toff + u]; np = fmaf(v, v, np); }
        }
        __syncthreads();
    }
    atomicAdd(&g_gram[(((size_t)b * HEADS_ + h) * 16 + i) * 16 + j], acc);
    np += __shfl_down_sync(0xffffffffu, np, 4);
    np += __shfl_down_sync(0xffffffffu, np, 2);
    np += __shfl_down_sync(0xffffffffu, np, 1);
    if ((tid & 7) == 0) atomicAdd(&g_nrm[((size_t)b * HEADS_ + h) * 32 + tgt], np);
}

// ===== attention part 2: normalize + temperature + softmax =====
__global__ void attn_soft(const float* __restrict__ temp)
{
    __shared__ float gm[16][17];
    int h = blockIdx.x, b = blockIdx.y;
    int tid = threadIdx.x;
    if (tid < 256) {
        int i = tid >> 4, j = tid & 15;
        const float* nr = g_nrm + ((size_t)b * HEADS_ + h) * 32;
        float invq = 1.f / fmaxf(sqrtf(nr[i]), 1e-12f);
        float invk = 1.f / fmaxf(sqrtf(nr[16 + j]), 1e-12f);
        gm[i][j] = g_gram[(((size_t)b * HEADS_ + h) * 16 + i) * 16 + j]
                   * invq * invk * temp[h];
    }
    __syncthreads();
    if (tid < 16) {
        int ii = tid;
        float m = -1e30f;
        for (int jj = 0; jj < 16; jj++) m = fmaxf(m, gm[ii][jj]);
        float e[16], ssum = 0.f;
        for (int jj = 0; jj < 16; jj++) { e[jj] = expf(gm[ii][jj] - m); ssum += e[jj]; }
        float inv = 1.f / ssum;
        for (int jj = 0; jj < 16; jj++)
            g_attn[(((size_t)b * HEADS_ + h) * 16 + ii) * 16 + jj] = e[jj] * inv;
    }
}

extern "C" void kernel_launch(void* const* d_in, const int* in_sizes, int n_in,
                              void* d_out, int out_size)
{
    const float* x        = (const float*)d_in[0];
    const float* y        = (const float*)d_in[1];
    const float* w_pos    = (const float*)d_in[2];
    const float* w_qv     = (const float*)d_in[3];
    const float* w_qv_dw  = (const float*)d_in[4];
    const float* w_kv     = (const float*)d_in[5];
    const float* w_kv_dw  = (const float*)d_in[6];
    const float* w_proj   = (const float*)d_in[7];
    const float* w_fuse   = (const float*)d_in[8];
    const float* b_fuse   = (const float*)d_in[9];
    const float* temp     = (const float*)d_in[10];
    float* out = (float*)d_out;

    void *pxh, *pyh, *pv, *pwq, *pwk, *pwft, *pwfin;
    cudaGetSymbolAddress(&pxh, g_xh);
    cudaGetSymbolAddress(&pyh, g_yh);
    cudaGetSymbolAddress(&pv, g_v);
    cudaGetSymbolAddress(&pwq, g_wq);
    cudaGetSymbolAddress(&pwk, g_wk);
    cudaGetSymbolAddress(&pwft, g_wft);
    cudaGetSymbolAddress(&pwfin, g_wfin);

    cudaFuncSetAttribute(mma_gemm_qk, cudaFuncAttributeMaxDynamicSharedMemorySize, SMEM_G);
    cudaFuncSetAttribute(mma_gemm, cudaFuncAttributeMaxDynamicSharedMemorySize, SMEM_G);
    cudaFuncSetAttribute(fuse_mma, cudaFuncAttributeMaxDynamicSharedMemorySize, SMEM_F);

    pack_a<<<(C2_ * 96 + 255) / 256, 256>>>(w_qv, (__half*)pwq, 96);
    pack_a<<<(C2_ * 96 + 255) / 256, 256>>>(w_kv, (__half*)pwk, 96);
    pack_fuse<<<(12 * 9 * 96 * 16 + 255) / 256, 256>>>(w_fuse, (__half*)pwft);

    // merged q/k GEMMs (fp32 in, fp16 out + write-through of x,y as fp16)
    mma_gemm_qk<<<dim3(128, 2 * B_), 768, SMEM_G>>>(
        x, y, (const __half*)pwq, (const __half*)pwk);
    // depthwise both branches, 8 px/thread
    dw3x3_kernel<<<dim3(8, C2_, 2 * B_), 256>>>(w_qv_dw, w_kv_dw);
    // v = fuse3x3(cat(v0, v_)) + bias
    fuse_mma<<<dim3(64, B_), 768, SMEM_F>>>((const __half*)pwft, b_fuse);
    // attention
    attn_part<<<dim3(HEADS_, B_, NSPLIT), 256>>>();
    attn_soft<<<dim3(HEADS_, B_), 256>>>(temp);
    // per-batch fused final weights
    pack_wfin<<<(B_ * C2_ * 288 + 255) / 256, 256>>>(w_proj, w_pos, (__half*)pwfin);
    // final: g_wfin_b @ [v; x; y] -> fp32 out
    mma_gemm<<<dim3(128, B_), 768, SMEM_G>>>(
        (const __half*)pv, (const __half*)pxh, (const __half*)pyh,
        (const __half*)pwfin, out, 288, 9 * 192 * APITCH);
}